// round 10
// baseline (speedup 1.0000x reference)
#include <cuda_runtime.h>
#include <cuda_fp16.h>
#include <cuda_bf16.h>

#define NNODES 100000
#define NEDGES 1600000
#define INF    128
#define HF     64     // HEADS*OUT_FEATS
#define NEG_SLOPE 0.2f
#define EPS_F  1e-16f

#define NGB2 ((NNODES + 127) / 128)          // 782 gemm blocks (128 nodes each)
#define SBLK 256
#define NSB  ((NNODES + SBLK - 1) / SBLK)    // 391 scan blocks

typedef unsigned long long u64;

// ---------------- static device scratch (no allocations allowed) ----------
// State-recycling invariant: g_counts and g_state are all-zero on entry to
// every kernel_launch call (BSS-zero initially; scan re-zeroes counts after
// consuming them, scatter re-zeroes the lookback states after scan).
__device__ __half g_hh[NNODES * HF];         // 12.8 MB projected features (fp16)
__device__ float4 g_el[NNODES];              // [N][4] left scores
__device__ float4 g_er[NNODES];              // [N][4] right scores
__device__ int    g_counts[NNODES];
__device__ int    g_cursor[NNODES];
__device__ int    g_rowptr[NNODES + 1];
__device__ int    g_psrc[NEDGES];            // src ids grouped by target
__device__ u64    g_state[NSB];              // lookback: (sum<<2)|{0,1,2}

// ---------------- helpers --------------------------------------------------
__device__ __forceinline__ unsigned f22u(float a, float b) {
    __half2 h = __floats2half2_rn(a, b);
    return *reinterpret_cast<unsigned*>(&h);
}

__device__ __forceinline__ void mma16816(float* c, unsigned a0, unsigned a1,
                                         unsigned a2, unsigned a3,
                                         unsigned b0, unsigned b1) {
    asm volatile(
        "mma.sync.aligned.m16n8k16.row.col.f32.f16.f16.f32 "
        "{%0,%1,%2,%3}, {%4,%5,%6,%7}, {%8,%9}, {%0,%1,%2,%3};"
        : "+f"(c[0]), "+f"(c[1]), "+f"(c[2]), "+f"(c[3])
        : "r"(a0), "r"(a1), "r"(a2), "r"(a3), "r"(b0), "r"(b1));
}

// ---------------- K1: h = feat @ W on tensor cores (HMMA fp16 -> f32) -----
// Block: 256 threads (8 warps), 128 nodes. A tile [128][128] fp16 and
// W^T [64][128] fp16 staged in smem with XOR swizzle (word ^ 4*(row&7))
// for conflict-free fragment loads. Warp w: rows [16w,16w+16) x n64 x k128
// = 64 mma.m16n8k16. Epilogue stages h in smem, writes h + el/er.
__global__ __launch_bounds__(256) void gemm_kernel(
    const float* __restrict__ feat, const float* __restrict__ W,
    const float* __restrict__ attL, const float* __restrict__ attR) {
    __shared__ uint4 smemU[3072];            // 48 KB
    unsigned* wA = reinterpret_cast<unsigned*>(smemU);        // 8192 words
    unsigned* wW = reinterpret_cast<unsigned*>(smemU + 2048); // 4096 words
    __half*   hW = reinterpret_cast<__half*>(wW);

    int tid = threadIdx.x;
    int base = blockIdx.x * 128;

    // --- stage A (feat -> fp16, swizzled). 2 threads per row. -------------
    {
        int row = tid >> 1, hs = tid & 1;
        int node = base + row;
        const float4* src =
            reinterpret_cast<const float4*>(feat + (size_t)node * INF + 64 * hs);
        int sw = 4 * (row & 7);
#pragma unroll
        for (int f = 0; f < 8; f++) {
            float4 v0, v1;
            if (node < NNODES) { v0 = src[2 * f]; v1 = src[2 * f + 1]; }
            else { v0 = make_float4(0,0,0,0); v1 = v0; }
            uint4 u;
            u.x = f22u(v0.x, v0.y);
            u.y = f22u(v0.z, v0.w);
            u.z = f22u(v1.x, v1.y);
            u.w = f22u(v1.z, v1.w);
            int kw = 32 * hs + 4 * f;                 // word base (mult of 4)
            *reinterpret_cast<uint4*>(&wA[row * 64 + (kw ^ sw)]) = u;
        }
    }

    // --- stage W^T (fp16, swizzled): sWt[n][k]. 2 threads per k-row. ------
    {
        int k = tid >> 1, nh = tid & 1;
        const float* wrow = W + k * HF + 32 * nh;
        int kwrd = k >> 1, ksel = k & 1;
#pragma unroll 8
        for (int i = 0; i < 32; i++) {
            int n = 32 * nh + i;
            hW[(n * 64 + (kwrd ^ (4 * (n & 7)))) * 2 + ksel] =
                __float2half_rn(wrow[i]);
        }
    }
    __syncthreads();

    // --- mma mainloop ------------------------------------------------------
    int lane = tid & 31, wrp = tid >> 5;
    int gid = lane >> 2, tg = lane & 3;
    int m0 = wrp * 16;
    int rA = m0 + gid, rA2 = rA + 8;
    int swA = 4 * gid;                       // (row&7)==gid for both rows

    float c[8][4];
#pragma unroll
    for (int j = 0; j < 8; j++)
#pragma unroll
        for (int q = 0; q < 4; q++) c[j][q] = 0.f;

#pragma unroll
    for (int ks = 0; ks < 8; ks++) {
        int kb = ks * 8 + tg;
        unsigned a0 = wA[rA  * 64 + (kb ^ swA)];
        unsigned a1 = wA[rA2 * 64 + (kb ^ swA)];
        unsigned a2 = wA[rA  * 64 + ((kb + 4) ^ swA)];
        unsigned a3 = wA[rA2 * 64 + ((kb + 4) ^ swA)];
#pragma unroll
        for (int j = 0; j < 8; j++) {
            int n = 8 * j + gid;             // (n&7)==gid -> same swizzle
            unsigned b0 = wW[n * 64 + (kb ^ swA)];
            unsigned b1 = wW[n * 64 + ((kb + 4) ^ swA)];
            mma16816(c[j], a0, a1, a2, a3, b0, b1);
        }
    }
    __syncthreads();                         // all warps done reading A tile

    // --- stage h (fp16) into reused A buffer: [128 rows][32 words] --------
#pragma unroll
    for (int j = 0; j < 8; j++) {
        int colw = 4 * j + tg;
        wA[rA  * 32 + (colw ^ swA)] = f22u(c[j][0], c[j][1]);
        wA[rA2 * 32 + (colw ^ swA)] = f22u(c[j][2], c[j][3]);
    }
    __syncthreads();

    // --- write h to global (coalesced uint4) ------------------------------
    {
        int row = tid >> 1, wsel = tid & 1;
        int node = base + row;
        if (node < NNODES) {
            uint4* dst = reinterpret_cast<uint4*>(g_hh + (size_t)node * HF);
            int sw = 4 * (row & 7);
#pragma unroll
            for (int m = 0; m < 4; m++) {
                int w = (16 * wsel + 4 * m) ^ sw;
                dst[4 * wsel + m] = *reinterpret_cast<uint4*>(&wA[row * 32 + w]);
            }
        }
    }

    // --- el/er: 512 (node,head) pairs, 2 per thread ------------------------
#pragma unroll
    for (int p = tid; p < 512; p += 256) {
        int row = p >> 2, head = p & 3;
        int node = base + row;
        if (node < NNODES) {
            int sw = 4 * (row & 7);
            float el = 0.f, er = 0.f;
#pragma unroll
            for (int m = 0; m < 8; m++) {
                unsigned v = wA[row * 32 + ((head * 8 + m) ^ sw)];
                float2 f = __half22float2(*reinterpret_cast<__half2*>(&v));
                el += f.x * attL[head * 16 + 2 * m] +
                      f.y * attL[head * 16 + 2 * m + 1];
                er += f.x * attR[head * 16 + 2 * m] +
                      f.y * attR[head * 16 + 2 * m + 1];
            }
            reinterpret_cast<float*>(g_el)[node * 4 + head] = el;
            reinterpret_cast<float*>(g_er)[node * 4 + head] = er;
        }
    }
}

// ---------------- K2: target-degree histogram (8 edges/thread) ------------
__global__ void count_kernel(const int* __restrict__ trg) {
    int e8 = blockIdx.x * blockDim.x + threadIdx.x;
    if (e8 >= NEDGES / 8) return;
    int4 t0 = reinterpret_cast<const int4*>(trg)[e8 * 2];
    int4 t1 = reinterpret_cast<const int4*>(trg)[e8 * 2 + 1];
    atomicAdd(&g_counts[t0.x], 1);
    atomicAdd(&g_counts[t0.y], 1);
    atomicAdd(&g_counts[t0.z], 1);
    atomicAdd(&g_counts[t0.w], 1);
    atomicAdd(&g_counts[t1.x], 1);
    atomicAdd(&g_counts[t1.y], 1);
    atomicAdd(&g_counts[t1.z], 1);
    atomicAdd(&g_counts[t1.w], 1);
}

// ---------------- K3: decoupled lookback scan, warp-parallel window -------
// Also re-zeroes g_counts after consuming (state recycling for next call).
__global__ __launch_bounds__(SBLK) void scan_kernel() {
    int b = blockIdx.x, tid = threadIdx.x;
    int lane = tid & 31, wid = tid >> 5;
    int i = b * SBLK + tid;
    int v = (i < NNODES) ? g_counts[i] : 0;

    // inclusive warp scan
    int x = v;
#pragma unroll
    for (int off = 1; off < 32; off <<= 1) {
        int u = __shfl_up_sync(0xFFFFFFFFu, x, off);
        if (lane >= off) x += u;
    }
    __shared__ int wsum[8], woff[8];
    __shared__ int s_prev;
    if (lane == 31) wsum[wid] = x;
    __syncthreads();

    if (tid < 32) {
        // scan the 8 warp sums in lanes 0..7
        int t = (lane < 8) ? wsum[lane] : 0;
        int s = t;
#pragma unroll
        for (int off = 1; off < 8; off <<= 1) {
            int u = __shfl_up_sync(0xFFFFFFFFu, s, off);
            if (lane >= off && lane < 8) s += u;
        }
        if (lane < 8) woff[lane] = s - t;
        int total = __shfl_sync(0xFFFFFFFFu, s, 7);

        if (b == 0) {
            if (lane == 0) {
                atomicExch(&g_state[0], ((u64)total << 2) | 2ull);
                s_prev = 0;
            }
        } else {
            if (lane == 0)
                atomicExch(&g_state[b], ((u64)total << 2) | 1ull);
            long long prev = 0;
            int look = b - 1;
            while (true) {
                int idx = look - lane;               // lane 0 = nearest pred
                u64 st = (idx >= 0) ? atomicAdd(&g_state[idx], 0ull) : 0ull;
                u64 fl = (idx >= 0) ? (st & 3ull) : 2ull;
                unsigned ready = __ballot_sync(0xFFFFFFFFu, fl != 0ull);
                if (ready != 0xFFFFFFFFu) { __nanosleep(20); continue; }
                unsigned pmask = __ballot_sync(0xFFFFFFFFu, fl == 2ull);
                int firstP = __ffs(pmask) - 1;       // -1 if all aggregates
                long long contrib =
                    (firstP < 0 || lane <= firstP) ? (long long)(st >> 2) : 0ll;
#pragma unroll
                for (int off = 16; off > 0; off >>= 1)
                    contrib += __shfl_down_sync(0xFFFFFFFFu, contrib, off);
                contrib = __shfl_sync(0xFFFFFFFFu, contrib, 0);
                prev += contrib;
                if (firstP >= 0) break;
                look -= 32;
            }
            if (lane == 0) {
                atomicExch(&g_state[b], ((u64)(prev + total) << 2) | 2ull);
                s_prev = (int)prev;
            }
        }
    }
    __syncthreads();
    if (i < NNODES) {
        int pos = s_prev + woff[wid] + x - v;  // global exclusive prefix
        g_rowptr[i] = pos;
        g_cursor[i] = pos;
        g_counts[i] = 0;                       // recycle for next call
        if (i == NNODES - 1) g_rowptr[NNODES] = NEDGES;
    }
}

// ---------------- K4: scatter src ids (8 edges/thread, high MLP) ----------
// Also recycles lookback state for the next call.
__global__ void scatter_kernel(const int* __restrict__ src,
                               const int* __restrict__ trg) {
    int e8 = blockIdx.x * blockDim.x + threadIdx.x;
    if (e8 < NSB) g_state[e8] = 0ull;          // reset for next call
    if (e8 >= NEDGES / 8) return;
    int4 t0 = reinterpret_cast<const int4*>(trg)[e8 * 2];
    int4 t1 = reinterpret_cast<const int4*>(trg)[e8 * 2 + 1];
    int4 s0 = reinterpret_cast<const int4*>(src)[e8 * 2];
    int4 s1 = reinterpret_cast<const int4*>(src)[e8 * 2 + 1];
    int p0 = atomicAdd(&g_cursor[t0.x], 1);
    int p1 = atomicAdd(&g_cursor[t0.y], 1);
    int p2 = atomicAdd(&g_cursor[t0.z], 1);
    int p3 = atomicAdd(&g_cursor[t0.w], 1);
    int p4 = atomicAdd(&g_cursor[t1.x], 1);
    int p5 = atomicAdd(&g_cursor[t1.y], 1);
    int p6 = atomicAdd(&g_cursor[t1.z], 1);
    int p7 = atomicAdd(&g_cursor[t1.w], 1);
    g_psrc[p0] = s0.x;
    g_psrc[p1] = s0.y;
    g_psrc[p2] = s0.z;
    g_psrc[p3] = s0.w;
    g_psrc[p4] = s1.x;
    g_psrc[p5] = s1.y;
    g_psrc[p6] = s1.z;
    g_psrc[p7] = s1.w;
}

// ---------------- K5: single-pass warp-per-node softmax + aggregation -----
// Unnormalized accumulate Sum(e_i * h_i); divide by Sum(e_i)+EPS at the end.
// Inner loop: 4 edges x 16B per iteration (jsub = lane>>3, chunk c = lane&7),
// then combine partials across jsub groups with shfl-xor.
__global__ __launch_bounds__(256) void agg_kernel(float* __restrict__ out) {
    __shared__ int   s_src[8][32];
    __shared__ float s_exp[8][32 * 4];

    int gw = (blockIdx.x * 256 + threadIdx.x) >> 5;   // node
    int lane = threadIdx.x & 31;
    int ws = (threadIdx.x >> 5);
    if (gw >= NNODES) return;

    int beg = g_rowptr[gw];
    int end = g_rowptr[gw + 1];
    float4 er = g_er[gw];
    int c = lane & 7;            // feature chunk: halfs [8c, 8c+8)
    int jsub = lane >> 3;        // edge sub-index within group of 4
    int head = c >> 1;           // head of this feature chunk

    float acc[8];
#pragma unroll
    for (int k = 0; k < 8; k++) acc[k] = 0.f;
    float4 dp = make_float4(0.f, 0.f, 0.f, 0.f);   // per-lane denom partials
    const char* hb = reinterpret_cast<const char*>(g_hh);

    for (int t0 = beg; t0 < end; t0 += 32) {
        int cnt = min(32, end - t0);
        int s = 0;
        float4 e4 = make_float4(0.f, 0.f, 0.f, 0.f);
        if (lane < cnt) {
            s = __ldg(&g_psrc[t0 + lane]);          // sequential coalesced
            float4 l = g_el[s];                     // 16B gather, L2-resident
            float sx = l.x + er.x, sy = l.y + er.y;
            float sz = l.z + er.z, sw = l.w + er.w;
            sx = sx > 0.f ? sx : NEG_SLOPE * sx;
            sy = sy > 0.f ? sy : NEG_SLOPE * sy;
            sz = sz > 0.f ? sz : NEG_SLOPE * sz;
            sw = sw > 0.f ? sw : NEG_SLOPE * sw;
            e4 = make_float4(__expf(sx), __expf(sy), __expf(sz), __expf(sw));
            dp.x += e4.x; dp.y += e4.y; dp.z += e4.z; dp.w += e4.w;
        }
        s_src[ws][lane] = s;                        // inactive lanes: 0, a=0
        reinterpret_cast<float4*>(s_exp[ws])[lane] = e4;
        __syncwarp();

        int nIter = (cnt + 3) >> 2;
#pragma unroll 2
        for (int j4 = 0; j4 < nIter; j4++) {
            int j = j4 * 4 + jsub;                  // j <= 31 always
            int sj = s_src[ws][j];
            float a = s_exp[ws][j * 4 + head];
            uint4 hv = *reinterpret_cast<const uint4*>(
                hb + (size_t)sj * 128 + c * 16);
            float2 f0 = __half22float2(*reinterpret_cast<__half2*>(&hv.x));
            float2 f1 = __half22float2(*reinterpret_cast<__half2*>(&hv.y));
            float2 f2 = __half22float2(*reinterpret_cast<__half2*>(&hv.z));
            float2 f3 = __half22float2(*reinterpret_cast<__half2*>(&hv.w));
            acc[0] = fmaf(f0.x, a, acc[0]);
            acc[1] = fmaf(f0.y, a, acc[1]);
            acc[2] = fmaf(f1.x, a, acc[2]);
            acc[3] = fmaf(f1.y, a, acc[3]);
            acc[4] = fmaf(f2.x, a, acc[4]);
            acc[5] = fmaf(f2.y, a, acc[5]);
            acc[6] = fmaf(f3.x, a, acc[6]);
            acc[7] = fmaf(f3.y, a, acc[7]);
        }
        __syncwarp();
    }

    // combine partial sums across the 4 jsub groups (lanes xor 8, 16)
#pragma unroll
    for (int k = 0; k < 8; k++) {
        acc[k] += __shfl_xor_sync(0xFFFFFFFFu, acc[k], 8);
        acc[k] += __shfl_xor_sync(0xFFFFFFFFu, acc[k], 16);
    }

    // reduce denom partials across all lanes
#pragma unroll
    for (int off = 16; off > 0; off >>= 1) {
        dp.x += __shfl_xor_sync(0xFFFFFFFFu, dp.x, off);
        dp.y += __shfl_xor_sync(0xFFFFFFFFu, dp.y, off);
        dp.z += __shfl_xor_sync(0xFFFFFFFFu, dp.z, off);
        dp.w += __shfl_xor_sync(0xFFFFFFFFu, dp.w, off);
    }
    float denom = (head == 0) ? dp.x : (head == 1) ? dp.y
                : (head == 2) ? dp.z : dp.w;
    float rd = 1.0f / (denom + EPS_F);

    if (jsub == 0) {                               // lanes 0..7 write the row
        float4* orow = reinterpret_cast<float4*>(out + (size_t)gw * HF + c * 8);
        orow[0] = make_float4(acc[0] * rd, acc[1] * rd, acc[2] * rd, acc[3] * rd);
        orow[1] = make_float4(acc[4] * rd, acc[5] * rd, acc[6] * rd, acc[7] * rd);
    }
}

// ---------------- launch ---------------------------------------------------
extern "C" void kernel_launch(void* const* d_in, const int* in_sizes, int n_in,
                              void* d_out, int out_size) {
    const float* feat = (const float*)d_in[0];
    const float* W    = (const float*)d_in[1];
    const float* attL = (const float*)d_in[2];
    const float* attR = (const float*)d_in[3];
    const int*   src  = (const int*)d_in[4];
    const int*   trg  = (const int*)d_in[5];
    float* out = (float*)d_out;

    // side stream + events, created once on the (uncaptured) correctness call
    static cudaStream_t s2 = 0;
    static cudaEvent_t  e0 = 0, e1 = 0;
    static bool ready = false;
    if (!ready) {
        bool ok = (cudaStreamCreateWithFlags(&s2, cudaStreamNonBlocking) == cudaSuccess)
               && (cudaEventCreateWithFlags(&e0, cudaEventDisableTiming) == cudaSuccess)
               && (cudaEventCreateWithFlags(&e1, cudaEventDisableTiming) == cudaSuccess);
        if (!ok) { s2 = 0; e0 = e1 = 0; }
        ready = true;
    }

    bool fork = (s2 != 0);
    if (fork) {
        cudaEventRecord(e0, 0);
        cudaStreamWaitEvent(s2, e0, 0);
    }

    // branch B (legacy stream): CSR build — launched first so gemm is the
    // 4th kernel launch (ncu -s 5 -c 1 lands on it; still overlaps via s2).
    count_kernel<<<(NEDGES / 8 + 255) / 256, 256>>>(trg);
    scan_kernel<<<NSB, SBLK>>>();
    scatter_kernel<<<(NEDGES / 8 + 255) / 256, 256>>>(src, trg);

    // branch A (side stream): projection GEMM (independent of CSR build)
    gemm_kernel<<<NGB2, 256, 0, fork ? s2 : 0>>>(feat, W, attL, attR);
    if (fork) cudaEventRecord(e1, s2);

    // join, then aggregate
    if (fork) cudaStreamWaitEvent(0, e1, 0);
    agg_kernel<<<(NNODES * 32 + 255) / 256, 256>>>(out);
}

// round 11
// speedup vs baseline: 1.6616x; 1.6616x over previous
#include <cuda_runtime.h>
#include <cuda_fp16.h>
#include <cuda_bf16.h>

#define NNODES 100000
#define NEDGES 1600000
#define INF    128
#define HF     64     // HEADS*OUT_FEATS
#define NEG_SLOPE 0.2f
#define EPS_F  1e-16f

#define NGB2 ((NNODES + 127) / 128)          // 782 gemm blocks (128 nodes each)
#define SBLK 256
#define NSB  ((NNODES + SBLK - 1) / SBLK)    // 391 scan blocks

typedef unsigned long long u64;

// ---------------- static device scratch (no allocations allowed) ----------
// State-recycling invariant: g_counts and g_state are all-zero on entry to
// every kernel_launch call (BSS-zero initially; scan re-zeroes counts after
// consuming them, scatter re-zeroes the lookback states after scan).
__device__ __half g_hh[NNODES * HF];         // 12.8 MB projected features (fp16)
__device__ float4 g_el[NNODES];              // [N][4] left scores
__device__ float4 g_er[NNODES];              // [N][4] right scores
__device__ int    g_counts[NNODES];
__device__ int    g_cursor[NNODES];
__device__ int    g_rowptr[NNODES + 1];
__device__ int    g_psrc[NEDGES];            // src ids grouped by target
__device__ u64    g_state[NSB];              // lookback: (sum<<2)|{0,1,2}
__device__ unsigned g_wt[4096];              // 16 KB: W^T fp16, pre-swizzled

// ---------------- helpers --------------------------------------------------
__device__ __forceinline__ unsigned f22u(float a, float b) {
    __half2 h = __floats2half2_rn(a, b);
    return *reinterpret_cast<unsigned*>(&h);
}

__device__ __forceinline__ void mma16816(float* c, unsigned a0, unsigned a1,
                                         unsigned a2, unsigned a3,
                                         unsigned b0, unsigned b1) {
    asm volatile(
        "mma.sync.aligned.m16n8k16.row.col.f32.f16.f16.f32 "
        "{%0,%1,%2,%3}, {%4,%5,%6,%7}, {%8,%9}, {%0,%1,%2,%3};"
        : "+f"(c[0]), "+f"(c[1]), "+f"(c[2]), "+f"(c[3])
        : "r"(a0), "r"(a1), "r"(a2), "r"(a3), "r"(b0), "r"(b1));
}

// ---------------- K0: one-shot W^T fp16 pre-swizzle -----------------------
// g_wt word layout: word(n, kwrd) at n*64 + (kwrd ^ (4*(n&7))), holding
// halfs k=2*kwrd (lo), k=2*kwrd+1 (hi). Same layout the gemm smem uses, so
// gemm's staging becomes a verbatim coalesced copy.
__global__ void wprep_kernel(const float* __restrict__ W) {
    int widx = blockIdx.x * blockDim.x + threadIdx.x;
    if (widx >= 4096) return;
    int n = widx >> 6, w = widx & 63;
    int kwrd = w ^ (4 * (n & 7));
    int k0 = 2 * kwrd;
    g_wt[widx] = f22u(W[k0 * HF + n], W[(k0 + 1) * HF + n]);
}

// ---------------- K1: h = feat @ W on tensor cores (HMMA fp16 -> f32) -----
// Block: 256 threads (8 warps), 128 nodes. A tile [128][128] fp16 staged
// with XOR swizzle (word ^ 4*(row&7)); W^T copied verbatim from g_wt.
// Warp w: rows [16w,16w+16) x n64 x k128 = 64 mma.m16n8k16.
__global__ __launch_bounds__(256) void gemm_kernel(
    const float* __restrict__ feat,
    const float* __restrict__ attL, const float* __restrict__ attR) {
    __shared__ uint4 smemU[3072];            // 48 KB
    unsigned* wA = reinterpret_cast<unsigned*>(smemU);        // 8192 words
    unsigned* wW = reinterpret_cast<unsigned*>(smemU + 2048); // 4096 words

    int tid = threadIdx.x;
    int base = blockIdx.x * 128;

    // --- stage A (feat -> fp16, swizzled). 2 threads per row. -------------
    {
        int row = tid >> 1, hs = tid & 1;
        int node = base + row;
        const float4* src =
            reinterpret_cast<const float4*>(feat + (size_t)node * INF + 64 * hs);
        int sw = 4 * (row & 7);
#pragma unroll
        for (int f = 0; f < 8; f++) {
            float4 v0, v1;
            if (node < NNODES) { v0 = src[2 * f]; v1 = src[2 * f + 1]; }
            else { v0 = make_float4(0,0,0,0); v1 = v0; }
            uint4 u;
            u.x = f22u(v0.x, v0.y);
            u.y = f22u(v0.z, v0.w);
            u.z = f22u(v1.x, v1.y);
            u.w = f22u(v1.z, v1.w);
            int kw = 32 * hs + 4 * f;                 // word base (mult of 4)
            *reinterpret_cast<uint4*>(&wA[row * 64 + (kw ^ sw)]) = u;
        }
    }

    // --- stage W^T: verbatim coalesced copy of pre-swizzled g_wt ----------
    {
        const uint4* src = reinterpret_cast<const uint4*>(g_wt);
        uint4* dst = reinterpret_cast<uint4*>(wW);
#pragma unroll
        for (int i = 0; i < 4; i++) dst[tid + 256 * i] = src[tid + 256 * i];
    }
    __syncthreads();

    // --- mma mainloop ------------------------------------------------------
    int lane = tid & 31, wrp = tid >> 5;
    int gid = lane >> 2, tg = lane & 3;
    int m0 = wrp * 16;
    int rA = m0 + gid, rA2 = rA + 8;
    int swA = 4 * gid;                       // (row&7)==gid for both rows

    float c[8][4];
#pragma unroll
    for (int j = 0; j < 8; j++)
#pragma unroll
        for (int q = 0; q < 4; q++) c[j][q] = 0.f;

#pragma unroll
    for (int ks = 0; ks < 8; ks++) {
        int kb = ks * 8 + tg;
        unsigned a0 = wA[rA  * 64 + (kb ^ swA)];
        unsigned a1 = wA[rA2 * 64 + (kb ^ swA)];
        unsigned a2 = wA[rA  * 64 + ((kb + 4) ^ swA)];
        unsigned a3 = wA[rA2 * 64 + ((kb + 4) ^ swA)];
#pragma unroll
        for (int j = 0; j < 8; j++) {
            int n = 8 * j + gid;             // (n&7)==gid -> same swizzle
            unsigned b0 = wW[n * 64 + (kb ^ swA)];
            unsigned b1 = wW[n * 64 + ((kb + 4) ^ swA)];
            mma16816(c[j], a0, a1, a2, a3, b0, b1);
        }
    }
    __syncthreads();                         // all warps done reading A tile

    // --- stage h (fp16) into reused A buffer: [128 rows][32 words] --------
#pragma unroll
    for (int j = 0; j < 8; j++) {
        int colw = 4 * j + tg;
        wA[rA  * 32 + (colw ^ swA)] = f22u(c[j][0], c[j][1]);
        wA[rA2 * 32 + (colw ^ swA)] = f22u(c[j][2], c[j][3]);
    }
    __syncthreads();

    // --- write h to global (coalesced uint4) ------------------------------
    {
        int row = tid >> 1, wsel = tid & 1;
        int node = base + row;
        if (node < NNODES) {
            uint4* dst = reinterpret_cast<uint4*>(g_hh + (size_t)node * HF);
            int sw = 4 * (row & 7);
#pragma unroll
            for (int m = 0; m < 4; m++) {
                int w = (16 * wsel + 4 * m) ^ sw;
                dst[4 * wsel + m] = *reinterpret_cast<uint4*>(&wA[row * 32 + w]);
            }
        }
    }

    // --- el/er: 512 (node,head) pairs, 2 per thread ------------------------
#pragma unroll
    for (int p = tid; p < 512; p += 256) {
        int row = p >> 2, head = p & 3;
        int node = base + row;
        if (node < NNODES) {
            int sw = 4 * (row & 7);
            float el = 0.f, er = 0.f;
#pragma unroll
            for (int m = 0; m < 8; m++) {
                unsigned v = wA[row * 32 + ((head * 8 + m) ^ sw)];
                float2 f = __half22float2(*reinterpret_cast<__half2*>(&v));
                el += f.x * attL[head * 16 + 2 * m] +
                      f.y * attL[head * 16 + 2 * m + 1];
                er += f.x * attR[head * 16 + 2 * m] +
                      f.y * attR[head * 16 + 2 * m + 1];
            }
            reinterpret_cast<float*>(g_el)[node * 4 + head] = el;
            reinterpret_cast<float*>(g_er)[node * 4 + head] = er;
        }
    }
}

// ---------------- K2: target-degree histogram (8 edges/thread) ------------
__global__ void count_kernel(const int* __restrict__ trg) {
    int e8 = blockIdx.x * blockDim.x + threadIdx.x;
    if (e8 >= NEDGES / 8) return;
    int4 t0 = reinterpret_cast<const int4*>(trg)[e8 * 2];
    int4 t1 = reinterpret_cast<const int4*>(trg)[e8 * 2 + 1];
    atomicAdd(&g_counts[t0.x], 1);
    atomicAdd(&g_counts[t0.y], 1);
    atomicAdd(&g_counts[t0.z], 1);
    atomicAdd(&g_counts[t0.w], 1);
    atomicAdd(&g_counts[t1.x], 1);
    atomicAdd(&g_counts[t1.y], 1);
    atomicAdd(&g_counts[t1.z], 1);
    atomicAdd(&g_counts[t1.w], 1);
}

// ---------------- K3: decoupled lookback scan, warp-parallel window -------
// Also re-zeroes g_counts after consuming (state recycling for next call).
__global__ __launch_bounds__(SBLK) void scan_kernel() {
    int b = blockIdx.x, tid = threadIdx.x;
    int lane = tid & 31, wid = tid >> 5;
    int i = b * SBLK + tid;
    int v = (i < NNODES) ? g_counts[i] : 0;

    // inclusive warp scan
    int x = v;
#pragma unroll
    for (int off = 1; off < 32; off <<= 1) {
        int u = __shfl_up_sync(0xFFFFFFFFu, x, off);
        if (lane >= off) x += u;
    }
    __shared__ int wsum[8], woff[8];
    __shared__ int s_prev;
    if (lane == 31) wsum[wid] = x;
    __syncthreads();

    if (tid < 32) {
        // scan the 8 warp sums in lanes 0..7
        int t = (lane < 8) ? wsum[lane] : 0;
        int s = t;
#pragma unroll
        for (int off = 1; off < 8; off <<= 1) {
            int u = __shfl_up_sync(0xFFFFFFFFu, s, off);
            if (lane >= off && lane < 8) s += u;
        }
        if (lane < 8) woff[lane] = s - t;
        int total = __shfl_sync(0xFFFFFFFFu, s, 7);

        if (b == 0) {
            if (lane == 0) {
                atomicExch(&g_state[0], ((u64)total << 2) | 2ull);
                s_prev = 0;
            }
        } else {
            if (lane == 0)
                atomicExch(&g_state[b], ((u64)total << 2) | 1ull);
            long long prev = 0;
            int look = b - 1;
            while (true) {
                int idx = look - lane;               // lane 0 = nearest pred
                u64 st = (idx >= 0) ? atomicAdd(&g_state[idx], 0ull) : 0ull;
                u64 fl = (idx >= 0) ? (st & 3ull) : 2ull;
                unsigned ready = __ballot_sync(0xFFFFFFFFu, fl != 0ull);
                if (ready != 0xFFFFFFFFu) { __nanosleep(20); continue; }
                unsigned pmask = __ballot_sync(0xFFFFFFFFu, fl == 2ull);
                int firstP = __ffs(pmask) - 1;       // -1 if all aggregates
                long long contrib =
                    (firstP < 0 || lane <= firstP) ? (long long)(st >> 2) : 0ll;
#pragma unroll
                for (int off = 16; off > 0; off >>= 1)
                    contrib += __shfl_down_sync(0xFFFFFFFFu, contrib, off);
                contrib = __shfl_sync(0xFFFFFFFFu, contrib, 0);
                prev += contrib;
                if (firstP >= 0) break;
                look -= 32;
            }
            if (lane == 0) {
                atomicExch(&g_state[b], ((u64)(prev + total) << 2) | 2ull);
                s_prev = (int)prev;
            }
        }
    }
    __syncthreads();
    if (i < NNODES) {
        int pos = s_prev + woff[wid] + x - v;  // global exclusive prefix
        g_rowptr[i] = pos;
        g_cursor[i] = pos;
        g_counts[i] = 0;                       // recycle for next call
        if (i == NNODES - 1) g_rowptr[NNODES] = NEDGES;
    }
}

// ---------------- K4: scatter src ids (8 edges/thread, high MLP) ----------
// Also recycles lookback state for the next call.
__global__ void scatter_kernel(const int* __restrict__ src,
                               const int* __restrict__ trg) {
    int e8 = blockIdx.x * blockDim.x + threadIdx.x;
    if (e8 < NSB) g_state[e8] = 0ull;          // reset for next call
    if (e8 >= NEDGES / 8) return;
    int4 t0 = reinterpret_cast<const int4*>(trg)[e8 * 2];
    int4 t1 = reinterpret_cast<const int4*>(trg)[e8 * 2 + 1];
    int4 s0 = reinterpret_cast<const int4*>(src)[e8 * 2];
    int4 s1 = reinterpret_cast<const int4*>(src)[e8 * 2 + 1];
    int p0 = atomicAdd(&g_cursor[t0.x], 1);
    int p1 = atomicAdd(&g_cursor[t0.y], 1);
    int p2 = atomicAdd(&g_cursor[t0.z], 1);
    int p3 = atomicAdd(&g_cursor[t0.w], 1);
    int p4 = atomicAdd(&g_cursor[t1.x], 1);
    int p5 = atomicAdd(&g_cursor[t1.y], 1);
    int p6 = atomicAdd(&g_cursor[t1.z], 1);
    int p7 = atomicAdd(&g_cursor[t1.w], 1);
    g_psrc[p0] = s0.x;
    g_psrc[p1] = s0.y;
    g_psrc[p2] = s0.z;
    g_psrc[p3] = s0.w;
    g_psrc[p4] = s1.x;
    g_psrc[p5] = s1.y;
    g_psrc[p6] = s1.z;
    g_psrc[p7] = s1.w;
}

// ---------------- K5: single-pass warp-per-node softmax + aggregation -----
// Unnormalized accumulate Sum(e_i * h_i); divide by Sum(e_i)+EPS at the end.
// Inner loop: 4 edges x 16B per iteration (jsub = lane>>3, chunk c = lane&7),
// then combine partials across jsub groups with shfl-xor.
__global__ __launch_bounds__(256) void agg_kernel(float* __restrict__ out) {
    __shared__ int   s_src[8][32];
    __shared__ float s_exp[8][32 * 4];

    int gw = (blockIdx.x * 256 + threadIdx.x) >> 5;   // node
    int lane = threadIdx.x & 31;
    int ws = (threadIdx.x >> 5);
    if (gw >= NNODES) return;

    int beg = g_rowptr[gw];
    int end = g_rowptr[gw + 1];
    float4 er = g_er[gw];
    int c = lane & 7;            // feature chunk: halfs [8c, 8c+8)
    int jsub = lane >> 3;        // edge sub-index within group of 4
    int head = c >> 1;           // head of this feature chunk

    float acc[8];
#pragma unroll
    for (int k = 0; k < 8; k++) acc[k] = 0.f;
    float4 dp = make_float4(0.f, 0.f, 0.f, 0.f);   // per-lane denom partials
    const char* hb = reinterpret_cast<const char*>(g_hh);

    for (int t0 = beg; t0 < end; t0 += 32) {
        int cnt = min(32, end - t0);
        int s = 0;
        float4 e4 = make_float4(0.f, 0.f, 0.f, 0.f);
        if (lane < cnt) {
            s = __ldg(&g_psrc[t0 + lane]);          // sequential coalesced
            float4 l = g_el[s];                     // 16B gather, L2-resident
            float sx = l.x + er.x, sy = l.y + er.y;
            float sz = l.z + er.z, sw = l.w + er.w;
            sx = sx > 0.f ? sx : NEG_SLOPE * sx;
            sy = sy > 0.f ? sy : NEG_SLOPE * sy;
            sz = sz > 0.f ? sz : NEG_SLOPE * sz;
            sw = sw > 0.f ? sw : NEG_SLOPE * sw;
            e4 = make_float4(__expf(sx), __expf(sy), __expf(sz), __expf(sw));
            dp.x += e4.x; dp.y += e4.y; dp.z += e4.z; dp.w += e4.w;
        }
        s_src[ws][lane] = s;                        // inactive lanes: 0, a=0
        reinterpret_cast<float4*>(s_exp[ws])[lane] = e4;
        __syncwarp();

        int nIter = (cnt + 3) >> 2;
#pragma unroll 2
        for (int j4 = 0; j4 < nIter; j4++) {
            int j = j4 * 4 + jsub;                  // j <= 31 always
            int sj = s_src[ws][j];
            float a = s_exp[ws][j * 4 + head];
            uint4 hv = *reinterpret_cast<const uint4*>(
                hb + (size_t)sj * 128 + c * 16);
            float2 f0 = __half22float2(*reinterpret_cast<__half2*>(&hv.x));
            float2 f1 = __half22float2(*reinterpret_cast<__half2*>(&hv.y));
            float2 f2 = __half22float2(*reinterpret_cast<__half2*>(&hv.z));
            float2 f3 = __half22float2(*reinterpret_cast<__half2*>(&hv.w));
            acc[0] = fmaf(f0.x, a, acc[0]);
            acc[1] = fmaf(f0.y, a, acc[1]);
            acc[2] = fmaf(f1.x, a, acc[2]);
            acc[3] = fmaf(f1.y, a, acc[3]);
            acc[4] = fmaf(f2.x, a, acc[4]);
            acc[5] = fmaf(f2.y, a, acc[5]);
            acc[6] = fmaf(f3.x, a, acc[6]);
            acc[7] = fmaf(f3.y, a, acc[7]);
        }
        __syncwarp();
    }

    // combine partial sums across the 4 jsub groups (lanes xor 8, 16)
#pragma unroll
    for (int k = 0; k < 8; k++) {
        acc[k] += __shfl_xor_sync(0xFFFFFFFFu, acc[k], 8);
        acc[k] += __shfl_xor_sync(0xFFFFFFFFu, acc[k], 16);
    }

    // reduce denom partials across all lanes
#pragma unroll
    for (int off = 16; off > 0; off >>= 1) {
        dp.x += __shfl_xor_sync(0xFFFFFFFFu, dp.x, off);
        dp.y += __shfl_xor_sync(0xFFFFFFFFu, dp.y, off);
        dp.z += __shfl_xor_sync(0xFFFFFFFFu, dp.z, off);
        dp.w += __shfl_xor_sync(0xFFFFFFFFu, dp.w, off);
    }
    float denom = (head == 0) ? dp.x : (head == 1) ? dp.y
                : (head == 2) ? dp.z : dp.w;
    float rd = 1.0f / (denom + EPS_F);

    if (jsub == 0) {                               // lanes 0..7 write the row
        float4* orow = reinterpret_cast<float4*>(out + (size_t)gw * HF + c * 8);
        orow[0] = make_float4(acc[0] * rd, acc[1] * rd, acc[2] * rd, acc[3] * rd);
        orow[1] = make_float4(acc[4] * rd, acc[5] * rd, acc[6] * rd, acc[7] * rd);
    }
}

// ---------------- launch ---------------------------------------------------
extern "C" void kernel_launch(void* const* d_in, const int* in_sizes, int n_in,
                              void* d_out, int out_size) {
    const float* feat = (const float*)d_in[0];
    const float* W    = (const float*)d_in[1];
    const float* attL = (const float*)d_in[2];
    const float* attR = (const float*)d_in[3];
    const int*   src  = (const int*)d_in[4];
    const int*   trg  = (const int*)d_in[5];
    float* out = (float*)d_out;

    // side stream + events, created once on the (uncaptured) correctness call
    static cudaStream_t s2 = 0;
    static cudaEvent_t  e0 = 0, e1 = 0;
    static bool ready = false;
    if (!ready) {
        bool ok = (cudaStreamCreateWithFlags(&s2, cudaStreamNonBlocking) == cudaSuccess)
               && (cudaEventCreateWithFlags(&e0, cudaEventDisableTiming) == cudaSuccess)
               && (cudaEventCreateWithFlags(&e1, cudaEventDisableTiming) == cudaSuccess);
        if (!ok) { s2 = 0; e0 = e1 = 0; }
        ready = true;
    }

    bool fork = (s2 != 0);
    if (fork) {
        cudaEventRecord(e0, 0);
        cudaStreamWaitEvent(s2, e0, 0);
    }

    cudaStream_t sg = fork ? s2 : 0;

    // branch A (side stream): W^T prep (launch 1); gemm follows in-order on
    // the same stream. Branch B (legacy stream): CSR build. Submission order
    // keeps gemm the 4th launch (ncu -s 5 -c 1 lands on it).
    wprep_kernel<<<16, 256, 0, sg>>>(W);
    count_kernel<<<(NEDGES / 8 + 255) / 256, 256>>>(trg);
    scan_kernel<<<NSB, SBLK>>>();
    gemm_kernel<<<NGB2, 256, 0, sg>>>(feat, attL, attR);
    if (fork) cudaEventRecord(e1, s2);
    scatter_kernel<<<(NEDGES / 8 + 255) / 256, 256>>>(src, trg);

    // join, then aggregate
    if (fork) cudaStreamWaitEvent(0, e1, 0);
    agg_kernel<<<(NNODES * 32 + 255) / 256, 256>>>(out);
}